// round 13
// baseline (speedup 1.0000x reference)
#include <cuda_runtime.h>
#include <cuda_bf16.h>
#include <cstdint>

#define N_NODES  50000
#define N_EDGES  50000
#define N_GRAPHS 1024
#define N_INC    400000
#define SCAN_B   196          // ceil(50000/256)

typedef __nv_bfloat16  bf16;
typedef __nv_bfloat162 bf162;

// ---------------- scratch (device globals) ----------------
__device__ bf16 g_acc_h[N_NODES * 256];
__device__ bf16 g_ef_h [N_NODES * 256];
__device__ bf16 g_hA_h [N_NODES * 256];
__device__ bf16 g_hB_h [N_NODES * 512];
__device__ bf16 g_W1t[256 * 128];       // bf16 W transposed [M][K]
__device__ bf16 g_W2t[512 * 256];
__device__ bf16 g_W3t[256 * 512];
__device__ bf16 g_xh [N_NODES * 128];   // bf16 copy of input x
__device__ float g_dinv[N_NODES];
__device__ float g_binv[N_EDGES];
__device__ float g_cnt [N_GRAPHS];
__device__ float g_pool[N_GRAPHS * 256];

// CSR machinery + degree-sorted permutations
__device__ int g_degE[N_EDGES];
__device__ int g_degN[N_NODES];
__device__ int g_offE[N_EDGES];
__device__ int g_offN[N_NODES];
__device__ int g_curE[N_EDGES];
__device__ int g_curN[N_NODES];
__device__ int g_nByE[N_INC];
__device__ int g_eByN[N_INC];
__device__ int g_part[2][256];
__device__ int g_hist[2][64];          // degree histograms (0=edges, 1=nodes)
__device__ int g_binCur[2][64];        // bin cursors (exclusive offsets)
__device__ int g_permE[N_EDGES];       // edge ids sorted by degree
__device__ int g_permN[N_NODES];       // node ids sorted by degree

__device__ __forceinline__ bf16* bufh(int s) {
    switch (s) {
        case 0: return g_acc_h;
        case 1: return g_ef_h;
        case 2: return g_hA_h;
        case 3: return g_hB_h;
        case 4: return g_W1t;
        case 5: return g_W2t;
        case 6: return g_W3t;
        default: return g_xh;
    }
}

__device__ __forceinline__ void red4(float* p, float4 v) {
    asm volatile("red.global.v4.f32.add [%0], {%1,%2,%3,%4};"
                 :: "l"(p), "f"(v.x), "f"(v.y), "f"(v.z), "f"(v.w) : "memory");
}

__device__ __forceinline__ void mma_bf16(float* c, const uint32_t* a, const uint32_t* b) {
    asm volatile(
        "mma.sync.aligned.m16n8k16.row.col.f32.bf16.bf16.f32 "
        "{%0,%1,%2,%3}, {%4,%5,%6,%7}, {%8,%9}, {%0,%1,%2,%3};"
        : "+f"(c[0]), "+f"(c[1]), "+f"(c[2]), "+f"(c[3])
        : "r"(a[0]), "r"(a[1]), "r"(a[2]), "r"(a[3]), "r"(b[0]), "r"(b[1]));
}

__device__ __forceinline__ void ldsm4(uint32_t* r, uint32_t addr) {
    asm volatile("ldmatrix.sync.aligned.m8n8.x4.shared.b16 {%0,%1,%2,%3}, [%4];"
                 : "=r"(r[0]), "=r"(r[1]), "=r"(r[2]), "=r"(r[3]) : "r"(addr));
}

__device__ __forceinline__ void cp16(uint32_t dst, const void* src, bool pred) {
    int sz = pred ? 16 : 0;
    asm volatile("cp.async.cg.shared.global [%0], [%1], 16, %2;"
                 :: "r"(dst), "l"(src), "r"(sz));
}
#define CP_COMMIT() asm volatile("cp.async.commit_group;")
#define CP_WAIT0()  asm volatile("cp.async.wait_group 0;")
#define CP_WAIT1()  asm volatile("cp.async.wait_group 1;")

__device__ __forceinline__ void acc8(float* a, uint4 v) {
    float2 f;
    f = __bfloat1622float2(*(bf162*)&v.x); a[0] += f.x; a[1] += f.y;
    f = __bfloat1622float2(*(bf162*)&v.y); a[2] += f.x; a[3] += f.y;
    f = __bfloat1622float2(*(bf162*)&v.z); a[4] += f.x; a[5] += f.y;
    f = __bfloat1622float2(*(bf162*)&v.w); a[6] += f.x; a[7] += f.y;
}

__device__ __forceinline__ uint4 pack8(const float* a) {
    uint4 r;
    *(bf162*)&r.x = __float22bfloat162_rn(make_float2(a[0], a[1]));
    *(bf162*)&r.y = __float22bfloat162_rn(make_float2(a[2], a[3]));
    *(bf162*)&r.z = __float22bfloat162_rn(make_float2(a[4], a[5]));
    *(bf162*)&r.w = __float22bfloat162_rn(make_float2(a[6], a[7]));
    return r;
}

// ---------------- init (zero counters) + conversions, fused ----------------
#define CONV_W1  (256 * 128)
#define CONV_W2  (512 * 256)
#define CONV_W3  (256 * 512)
#define CONV_X   (N_NODES * 128)
#define CONV_TOT (CONV_W1 + CONV_W2 + CONV_W3 + CONV_X)
__global__ void init_conv(const float* __restrict__ W1, const float* __restrict__ W2,
                          const float* __restrict__ W3, const float* __restrict__ x) {
    int i = blockIdx.x * 256 + threadIdx.x;
    if (i < 262144) {
        if (i < N_EDGES)        g_degE[i] = 0;
        if (i < N_NODES)        g_degN[i] = 0;
        if (i < N_GRAPHS)       g_cnt[i]  = 0.f;
        if (i < N_GRAPHS * 256) g_pool[i] = 0.f;
        if (i < 128)            g_hist[i >> 6][i & 63] = 0;
    }
    if (i >= CONV_TOT) return;
    if (i < CONV_W1) {
        int m = i >> 7, k = i & 127;
        g_W1t[i] = __float2bfloat16(W1[k * 256 + m]);
    } else if (i < CONV_W1 + CONV_W2) {
        int j = i - CONV_W1;
        int m = j >> 8, k = j & 255;
        g_W2t[j] = __float2bfloat16(W2[k * 512 + m]);
    } else if (i < CONV_W1 + CONV_W2 + CONV_W3) {
        int j = i - CONV_W1 - CONV_W2;
        int m = j >> 9, k = j & 511;
        g_W3t[j] = __float2bfloat16(W3[k * 256 + m]);
    } else {
        int j = i - CONV_W1 - CONV_W2 - CONV_W3;
        g_xh[j] = __float2bfloat16(x[j]);
    }
}

// ---------------- degrees + graph counts ----------------
__global__ void degcnt_k(const int* __restrict__ nidx, const int* __restrict__ eidx,
                         const int* __restrict__ batch) {
    int i = blockIdx.x * blockDim.x + threadIdx.x;
    if (i < N_INC) {
        atomicAdd(&g_degN[nidx[i]], 1);
        atomicAdd(&g_degE[eidx[i]], 1);
    }
    if (i < N_NODES) atomicAdd(&g_cnt[batch[i]], 1.f);
}

// scan1 + per-block degree histogram
__global__ void __launch_bounds__(256) scan1_k() {
    __shared__ int sm[256];
    __shared__ int hist[64];
    const int w = blockIdx.y;
    const int* cnt = w ? g_degN : g_degE;
    const int i = blockIdx.x * 256 + threadIdx.x;
    const int t = threadIdx.x;
    const int v = (i < N_EDGES) ? cnt[i] : 0;
    sm[t] = v;
    if (t < 64) hist[t] = 0;
    __syncthreads();
    if (i < N_EDGES) atomicAdd(&hist[v < 63 ? v : 63], 1);
    for (int s = 128; s > 0; s >>= 1) {
        if (t < s) sm[t] += sm[t + s];
        __syncthreads();
    }
    if (t == 0) g_part[w][blockIdx.x] = sm[0];
    if (t < 64 && hist[t]) atomicAdd(&g_hist[w][t], hist[t]);
}

// scan2: scan block partials + convert histograms to bin offsets
__global__ void __launch_bounds__(256) scan2_k() {
    __shared__ int sm[256];
    __shared__ int hb[2][64];
    const int t = threadIdx.x;
    for (int w = 0; w < 2; w++) {
        int v = (t < SCAN_B) ? g_part[w][t] : 0;
        sm[t] = v;
        __syncthreads();
        for (int d = 1; d < 256; d <<= 1) {
            int u = (t >= d) ? sm[t - d] : 0;
            __syncthreads();
            sm[t] += u;
            __syncthreads();
        }
        if (t < SCAN_B) g_part[w][t] = sm[t] - v;
        __syncthreads();
    }
    if (t < 128) hb[t >> 6][t & 63] = g_hist[t >> 6][t & 63];
    __syncthreads();
    if (t < 128) {
        int w2 = t >> 6, b = t & 63;
        int run = 0;
        for (int q = 0; q < b; q++) run += hb[w2][q];
        g_binCur[w2][b] = run;
    }
}

// scan3 + inverse degrees + degree-sorted permutation placement
__global__ void __launch_bounds__(256) scan3_k() {
    __shared__ int sm[256];
    const int w = blockIdx.y;
    const int* cnt = w ? g_degN : g_degE;
    int* offs = w ? g_offN : g_offE;
    int* cur  = w ? g_curN : g_curE;
    int* perm = w ? g_permN : g_permE;
    float* invb = w ? g_dinv : g_binv;
    const int i = blockIdx.x * 256 + threadIdx.x;
    const int t = threadIdx.x;
    const int v = (i < N_EDGES) ? cnt[i] : 0;
    sm[t] = v;
    __syncthreads();
    for (int d = 1; d < 256; d <<= 1) {
        int u = (t >= d) ? sm[t - d] : 0;
        __syncthreads();
        sm[t] += u;
        __syncthreads();
    }
    if (i < N_EDGES) {
        int e = sm[t] - v + g_part[w][blockIdx.x];
        offs[i] = e;
        cur[i]  = e;
        invb[i] = v > 0 ? 1.f / (float)v : 0.f;
        int p = atomicAdd(&g_binCur[w][v < 63 ? v : 63], 1);
        perm[p] = i;
    }
}

__global__ void build_k(const int* __restrict__ nidx, const int* __restrict__ eidx) {
    int i = blockIdx.x * blockDim.x + threadIdx.x;
    if (i >= N_INC) return;
    const int n = nidx[i], e = eidx[i];
    int pe = atomicAdd(&g_curE[e], 1);
    g_nByE[pe] = n;
    int pn = atomicAdd(&g_curN[n], 1);
    g_eByN[pn] = e;
}

// ---------------- gathers (bf16, 8-deep pipeline, degree-sorted order) ----------
__global__ void __launch_bounds__(256) gath_n2e_h(int inSel, int log2q) {
    const uint4* in = (const uint4*)bufh(inSel);
    const int t = threadIdx.x;
    const int j = t & ((1 << log2q) - 1);
    const int e = g_permE[blockIdx.x * (256 >> log2q) + (t >> log2q)];
    const int start = g_offE[e];
    const int d     = g_degE[e];
    float a[8] = {0.f, 0.f, 0.f, 0.f, 0.f, 0.f, 0.f, 0.f};
    int k = 0;
    for (; k + 7 < d; k += 8) {
        int nn[8];
#pragma unroll
        for (int u = 0; u < 8; u++) nn[u] = __ldg(&g_nByE[start + k + u]);
        uint4 vv[8];
#pragma unroll
        for (int u = 0; u < 8; u++) vv[u] = __ldg(&in[((size_t)nn[u] << log2q) + j]);
#pragma unroll
        for (int u = 0; u < 8; u++) acc8(a, vv[u]);
    }
    for (; k + 3 < d; k += 4) {
        int nn[4];
#pragma unroll
        for (int u = 0; u < 4; u++) nn[u] = __ldg(&g_nByE[start + k + u]);
        uint4 vv[4];
#pragma unroll
        for (int u = 0; u < 4; u++) vv[u] = __ldg(&in[((size_t)nn[u] << log2q) + j]);
#pragma unroll
        for (int u = 0; u < 4; u++) acc8(a, vv[u]);
    }
    for (; k < d; k++)
        acc8(a, __ldg(&in[((size_t)__ldg(&g_nByE[start + k]) << log2q) + j]));
    const float bw = g_binv[e];
#pragma unroll
    for (int r = 0; r < 8; r++) a[r] *= bw;
    ((uint4*)g_ef_h)[((size_t)e << log2q) + j] = pack8(a);
}

__global__ void __launch_bounds__(256) gath_e2n_h(
    int outSel, int log2q, int doEpi, const float* __restrict__ bias,
    int doPool, const int* __restrict__ batch) {
    uint4* outb = (uint4*)bufh(outSel);
    const uint4* ef = (const uint4*)g_ef_h;
    const int t = threadIdx.x;
    const int j = t & ((1 << log2q) - 1);
    const int n = g_permN[blockIdx.x * (256 >> log2q) + (t >> log2q)];
    const int start = g_offN[n];
    const int d     = g_degN[n];
    float a[8] = {0.f, 0.f, 0.f, 0.f, 0.f, 0.f, 0.f, 0.f};
    int k = 0;
    for (; k + 7 < d; k += 8) {
        int ee[8];
#pragma unroll
        for (int u = 0; u < 8; u++) ee[u] = __ldg(&g_eByN[start + k + u]);
        uint4 vv[8];
#pragma unroll
        for (int u = 0; u < 8; u++) vv[u] = __ldg(&ef[((size_t)ee[u] << log2q) + j]);
#pragma unroll
        for (int u = 0; u < 8; u++) acc8(a, vv[u]);
    }
    for (; k + 3 < d; k += 4) {
        int ee[4];
#pragma unroll
        for (int u = 0; u < 4; u++) ee[u] = __ldg(&g_eByN[start + k + u]);
        uint4 vv[4];
#pragma unroll
        for (int u = 0; u < 4; u++) vv[u] = __ldg(&ef[((size_t)ee[u] << log2q) + j]);
#pragma unroll
        for (int u = 0; u < 4; u++) acc8(a, vv[u]);
    }
    for (; k < d; k++)
        acc8(a, __ldg(&ef[((size_t)__ldg(&g_eByN[start + k]) << log2q) + j]));
    const float ds = g_dinv[n];
#pragma unroll
    for (int r = 0; r < 8; r++) a[r] *= ds;
    if (doEpi) {
        float4 bb0 = ((const float4*)bias)[2 * j];
        float4 bb1 = ((const float4*)bias)[2 * j + 1];
        a[0] = fmaxf(a[0] + bb0.x, 0.f); a[1] = fmaxf(a[1] + bb0.y, 0.f);
        a[2] = fmaxf(a[2] + bb0.z, 0.f); a[3] = fmaxf(a[3] + bb0.w, 0.f);
        a[4] = fmaxf(a[4] + bb1.x, 0.f); a[5] = fmaxf(a[5] + bb1.y, 0.f);
        a[6] = fmaxf(a[6] + bb1.z, 0.f); a[7] = fmaxf(a[7] + bb1.w, 0.f);
    }
    if (doPool) {
        float* dst = &g_pool[(batch[n] << 8) + 8 * j];
        red4(dst,     make_float4(a[0], a[1], a[2], a[3]));
        red4(dst + 4, make_float4(a[4], a[5], a[6], a[7]));
    } else {
        outb[((size_t)n << log2q) + j] = pack8(a);
    }
}

// ---------------- BF16 GEMM: 3-stage cp.async, 1 sync/iter, ldmatrix ------------
#define HS 20
#define STAGE_U (128 * HS)
#define STAGE_BYTES (STAGE_U * 4)
#define NSTG 3
#define GEMM_SMEM (NSTG * STAGE_BYTES * 2)
__global__ void __launch_bounds__(256) gemm_bf(
    int Asel, int Wsel, const float* __restrict__ bias, int outSel,
    int N, int K, int M, int doEpi) {
    const bf16* A  = bufh(Asel);
    const bf16* Wt = bufh(Wsel);
    bf16* C = bufh(outSel);

    extern __shared__ uint32_t dyn[];
    uint32_t* As_u = dyn;
    uint32_t* Bs_u = dyn + NSTG * STAGE_U;

    const int tid  = threadIdx.x;
    const int lane = tid & 31;
    const int warp = tid >> 5;
    const int wm = (warp & 3) * 32;
    const int wn = (warp >> 2) * 64;
    const int grp = lane >> 2;
    const int tig = lane & 3;

    const int rowBase = blockIdx.x * 128;
    const int colBase = blockIdx.y * 128;

    const int lr  = tid >> 1;
    const int lkb = (tid & 1) * 32;
    const int grow = rowBase + lr;
    const int gcol = colBase + lr;
    const bool aok = grow < N;

    uint32_t smA = (uint32_t)__cvta_generic_to_shared(As_u);
    uint32_t smB = (uint32_t)__cvta_generic_to_shared(Bs_u);
    uint32_t aBase = smA + lr * 80 + lkb;
    uint32_t bBase = smB + lr * 80 + lkb;
    const char* aSrc0 = (const char*)(A + (size_t)(aok ? grow : 0) * K) + lkb;
    const char* bSrc0 = (const char*)(Wt + (size_t)gcol * K) + lkb;

    uint32_t aAddr[2], bAddr[4];
#pragma unroll
    for (int mt = 0; mt < 2; mt++) {
        int row = wm + mt * 16 + ((lane >> 3) & 1) * 8 + (lane & 7);
        aAddr[mt] = smA + (row * HS + (lane >> 4) * 4) * 4;
    }
#pragma unroll
    for (int p = 0; p < 4; p++) {
        int row = wn + p * 16 + ((lane >> 4) & 1) * 8 + (lane & 7);
        bAddr[p] = smB + (row * HS + ((lane >> 3) & 1) * 4) * 4;
    }

    float acc[2][8][4];
#pragma unroll
    for (int mt = 0; mt < 2; mt++)
#pragma unroll
        for (int nt = 0; nt < 8; nt++)
#pragma unroll
            for (int r = 0; r < 4; r++) acc[mt][nt][r] = 0.f;

    const int nst = K >> 5;
#pragma unroll
    for (int s = 0; s < 2; s++) {
        const int off = s * 64;
        cp16(aBase + s * STAGE_BYTES,      aSrc0 + off,      aok);
        cp16(aBase + s * STAGE_BYTES + 16, aSrc0 + off + 16, aok);
        cp16(bBase + s * STAGE_BYTES,      bSrc0 + off,      true);
        cp16(bBase + s * STAGE_BYTES + 16, bSrc0 + off + 16, true);
        CP_COMMIT();
    }

    int st = 0, sl = 2;
    for (int i = 0; i < nst; i++) {
        if (i + 1 < nst) { CP_WAIT1(); } else { CP_WAIT0(); }
        __syncthreads();
        if (i + 2 < nst) {
            const int off = (i + 2) * 64;
            cp16(aBase + sl * STAGE_BYTES,      aSrc0 + off,      aok);
            cp16(aBase + sl * STAGE_BYTES + 16, aSrc0 + off + 16, aok);
            cp16(bBase + sl * STAGE_BYTES,      bSrc0 + off,      true);
            cp16(bBase + sl * STAGE_BYTES + 16, bSrc0 + off + 16, true);
            CP_COMMIT();
        }
        const uint32_t stOff = st * STAGE_BYTES;
#pragma unroll
        for (int kk2 = 0; kk2 < 16; kk2 += 8) {
            const uint32_t kOff = stOff + kk2 * 4;
            uint32_t af[2][4], bq[4][4];
#pragma unroll
            for (int mt = 0; mt < 2; mt++) ldsm4(af[mt], aAddr[mt] + kOff);
#pragma unroll
            for (int p = 0; p < 4; p++)    ldsm4(bq[p],  bAddr[p] + kOff);
#pragma unroll
            for (int mt = 0; mt < 2; mt++)
#pragma unroll
                for (int p = 0; p < 4; p++) {
                    mma_bf16(acc[mt][2 * p],     af[mt], &bq[p][0]);
                    mma_bf16(acc[mt][2 * p + 1], af[mt], &bq[p][2]);
                }
        }
        st = (st == NSTG - 1) ? 0 : st + 1;
        sl = (sl == NSTG - 1) ? 0 : sl + 1;
    }

#pragma unroll
    for (int mt = 0; mt < 2; mt++) {
        const int r0 = rowBase + wm + mt * 16 + grp;
        const int r1 = r0 + 8;
#pragma unroll
        for (int nt = 0; nt < 8; nt++) {
            const int col = colBase + wn + nt * 8 + tig * 2;
            float v0 = acc[mt][nt][0], v1 = acc[mt][nt][1];
            float v2 = acc[mt][nt][2], v3 = acc[mt][nt][3];
            if (doEpi) {
                const float bb0 = bias[col], bb1 = bias[col + 1];
                v0 = fmaxf(v0 + bb0, 0.f); v1 = fmaxf(v1 + bb1, 0.f);
                v2 = fmaxf(v2 + bb0, 0.f); v3 = fmaxf(v3 + bb1, 0.f);
            }
            if (r0 < N)
                *(bf162*)(C + (size_t)r0 * M + col) =
                    __float22bfloat162_rn(make_float2(v0, v1));
            if (r1 < N)
                *(bf162*)(C + (size_t)r1 * M + col) =
                    __float22bfloat162_rn(make_float2(v2, v3));
        }
    }
}

// ---------------- final MLP ----------------
__global__ void __launch_bounds__(256) mlp_k(
    const float* __restrict__ Wl1, const float* __restrict__ bl1,
    const float* __restrict__ Wl2, const float* __restrict__ bl2,
    float* __restrict__ out) {
    __shared__ float sp[256];
    __shared__ float red[128];
    const int g = blockIdx.x;
    const int t = threadIdx.x;

    const float ic = 1.f / fmaxf(g_cnt[g], 1.f);
    sp[t] = g_pool[(g << 8) + t] * ic;
    __syncthreads();

    if (t < 128) {
        float a = bl1[t];
#pragma unroll 8
        for (int k = 0; k < 256; k++) a = fmaf(sp[k], Wl1[k * 128 + t], a);
        red[t] = fmaxf(a, 0.f) * Wl2[t];
    }
    __syncthreads();
    for (int s = 64; s > 0; s >>= 1) {
        if (t < s) red[t] += red[t + s];
        __syncthreads();
    }
    if (t == 0) out[g] = red[0] + bl2[0];
}

extern "C" void kernel_launch(void* const* d_in, const int* in_sizes, int n_in,
                              void* d_out, int out_size) {
    const float* x     = (const float*)d_in[0];
    const int*   hei   = (const int*)d_in[1];    // int32 (JAX x64-disabled)
    const int*   batch = (const int*)d_in[2];
    const float *W1  = (const float*)d_in[3],  *b1  = (const float*)d_in[4];
    const float *W2  = (const float*)d_in[5],  *b2  = (const float*)d_in[6];
    const float *W3  = (const float*)d_in[7],  *b3  = (const float*)d_in[8];
    const float *Wl1 = (const float*)d_in[9],  *bl1 = (const float*)d_in[10];
    const float *Wl2 = (const float*)d_in[11], *bl2 = (const float*)d_in[12];
    const int* nidx = hei;
    const int* eidx = hei + N_INC;
    float* out = (float*)d_out;

    cudaFuncSetAttribute(gemm_bf, cudaFuncAttributeMaxDynamicSharedMemorySize,
                         GEMM_SMEM);

    // ---- setup (counting sort fused into scan chain) ----
    init_conv<<<(CONV_TOT + 255) / 256, 256>>>(W1, W2, W3, x);
    degcnt_k<<<(N_INC + 255) / 256, 256>>>(nidx, eidx, batch);
    scan1_k<<<dim3(SCAN_B, 2), 256>>>();
    scan2_k<<<1, 256>>>();
    scan3_k<<<dim3(SCAN_B, 2), 256>>>();
    build_k<<<(N_INC + 255) / 256, 256>>>(nidx, eidx);

    // ---- Layer 1 (gather-first, dim 128 bf16; K=128 -> M=256) ----
    gath_n2e_h<<<N_EDGES / 16, 256>>>(7, 4);
    gath_e2n_h<<<N_NODES / 16, 256>>>(0, 4, 0, nullptr, 0, nullptr);
    gemm_bf<<<dim3(391, 2), 256, GEMM_SMEM>>>(0, 4, b1, 2, N_NODES, 128, 256, 1);

    // ---- Layer 2 (gather-first, dim 256; K=256 -> M=512) ----
    gath_n2e_h<<<N_EDGES / 8, 256>>>(2, 5);
    gath_e2n_h<<<N_NODES / 8, 256>>>(0, 5, 0, nullptr, 0, nullptr);
    gemm_bf<<<dim3(391, 4), 256, GEMM_SMEM>>>(0, 5, b2, 3, N_NODES, 256, 512, 1);

    // ---- Layer 3 (gemm-first; K=512 -> M=256; epi + pool fused into e2n) ----
    gemm_bf<<<dim3(391, 2), 256, GEMM_SMEM>>>(3, 6, nullptr, 0, N_NODES, 512, 256, 0);
    gath_n2e_h<<<N_EDGES / 8, 256>>>(0, 5);
    gath_e2n_h<<<N_NODES / 8, 256>>>(2, 5, 1, b3, 1, batch);

    // ---- MLP head ----
    mlp_k<<<N_GRAPHS, 256>>>(Wl1, bl1, Wl2, bl2, out);
}

// round 14
// speedup vs baseline: 1.0397x; 1.0397x over previous
#include <cuda_runtime.h>
#include <cuda_bf16.h>
#include <cstdint>

#define N_NODES  50000
#define N_EDGES  50000
#define N_GRAPHS 1024
#define N_INC    400000
#define OFF_B    196          // ceil(50000/256)

typedef __nv_bfloat16  bf16;
typedef __nv_bfloat162 bf162;

// ---------------- scratch (device globals) ----------------
__device__ bf16 g_acc_h[N_NODES * 256];
__device__ bf16 g_ef_h [N_NODES * 256];
__device__ bf16 g_hA_h [N_NODES * 256];
__device__ bf16 g_hB_h [N_NODES * 512];
__device__ bf16 g_W1t[256 * 128];       // bf16 W transposed [M][K]
__device__ bf16 g_W2t[512 * 256];
__device__ bf16 g_W3t[256 * 512];
__device__ bf16 g_xh [N_NODES * 128];   // bf16 copy of input x
__device__ float g_dinv[N_NODES];
__device__ float g_binv[N_EDGES];
__device__ float g_cnt [N_GRAPHS];
__device__ float g_pool[N_GRAPHS * 256];

// CSR machinery
__device__ int g_degE[N_EDGES];
__device__ int g_degN[N_NODES];
__device__ int g_offE[N_EDGES];
__device__ int g_offN[N_NODES];
__device__ int g_curE[N_EDGES];
__device__ int g_curN[N_NODES];
__device__ int g_nByE[N_INC];
__device__ int g_eByN[N_INC];
__device__ int g_tot[2];               // global placement cursors (0=edges, 1=nodes)

__device__ __forceinline__ bf16* bufh(int s) {
    switch (s) {
        case 0: return g_acc_h;
        case 1: return g_ef_h;
        case 2: return g_hA_h;
        case 3: return g_hB_h;
        case 4: return g_W1t;
        case 5: return g_W2t;
        case 6: return g_W3t;
        default: return g_xh;
    }
}

__device__ __forceinline__ void red4(float* p, float4 v) {
    asm volatile("red.global.v4.f32.add [%0], {%1,%2,%3,%4};"
                 :: "l"(p), "f"(v.x), "f"(v.y), "f"(v.z), "f"(v.w) : "memory");
}

__device__ __forceinline__ void mma_bf16(float* c, const uint32_t* a, const uint32_t* b) {
    asm volatile(
        "mma.sync.aligned.m16n8k16.row.col.f32.bf16.bf16.f32 "
        "{%0,%1,%2,%3}, {%4,%5,%6,%7}, {%8,%9}, {%0,%1,%2,%3};"
        : "+f"(c[0]), "+f"(c[1]), "+f"(c[2]), "+f"(c[3])
        : "r"(a[0]), "r"(a[1]), "r"(a[2]), "r"(a[3]), "r"(b[0]), "r"(b[1]));
}

__device__ __forceinline__ void ldsm4(uint32_t* r, uint32_t addr) {
    asm volatile("ldmatrix.sync.aligned.m8n8.x4.shared.b16 {%0,%1,%2,%3}, [%4];"
                 : "=r"(r[0]), "=r"(r[1]), "=r"(r[2]), "=r"(r[3]) : "r"(addr));
}

__device__ __forceinline__ void cp16(uint32_t dst, const void* src, bool pred) {
    int sz = pred ? 16 : 0;
    asm volatile("cp.async.cg.shared.global [%0], [%1], 16, %2;"
                 :: "r"(dst), "l"(src), "r"(sz));
}
#define CP_COMMIT() asm volatile("cp.async.commit_group;")
#define CP_WAIT0()  asm volatile("cp.async.wait_group 0;")
#define CP_WAIT1()  asm volatile("cp.async.wait_group 1;")

__device__ __forceinline__ void acc8(float* a, uint4 v) {
    float2 f;
    f = __bfloat1622float2(*(bf162*)&v.x); a[0] += f.x; a[1] += f.y;
    f = __bfloat1622float2(*(bf162*)&v.y); a[2] += f.x; a[3] += f.y;
    f = __bfloat1622float2(*(bf162*)&v.z); a[4] += f.x; a[5] += f.y;
    f = __bfloat1622float2(*(bf162*)&v.w); a[6] += f.x; a[7] += f.y;
}

__device__ __forceinline__ uint4 pack8(const float* a) {
    uint4 r;
    *(bf162*)&r.x = __float22bfloat162_rn(make_float2(a[0], a[1]));
    *(bf162*)&r.y = __float22bfloat162_rn(make_float2(a[2], a[3]));
    *(bf162*)&r.z = __float22bfloat162_rn(make_float2(a[4], a[5]));
    *(bf162*)&r.w = __float22bfloat162_rn(make_float2(a[6], a[7]));
    return r;
}

// ---------------- init (zero counters) + conversions, fused ----------------
#define CONV_W1  (256 * 128)
#define CONV_W2  (512 * 256)
#define CONV_W3  (256 * 512)
#define CONV_X   (N_NODES * 128)
#define CONV_TOT (CONV_W1 + CONV_W2 + CONV_W3 + CONV_X)
__global__ void init_conv(const float* __restrict__ W1, const float* __restrict__ W2,
                          const float* __restrict__ W3, const float* __restrict__ x) {
    int i = blockIdx.x * 256 + threadIdx.x;
    if (i < 262144) {
        if (i < N_EDGES)        g_degE[i] = 0;
        if (i < N_NODES)        g_degN[i] = 0;
        if (i < N_GRAPHS)       g_cnt[i]  = 0.f;
        if (i < N_GRAPHS * 256) g_pool[i] = 0.f;
        if (i < 2)              g_tot[i] = 0;
    }
    if (i >= CONV_TOT) return;
    if (i < CONV_W1) {
        int m = i >> 7, k = i & 127;
        g_W1t[i] = __float2bfloat16(W1[k * 256 + m]);
    } else if (i < CONV_W1 + CONV_W2) {
        int j = i - CONV_W1;
        int m = j >> 8, k = j & 255;
        g_W2t[j] = __float2bfloat16(W2[k * 512 + m]);
    } else if (i < CONV_W1 + CONV_W2 + CONV_W3) {
        int j = i - CONV_W1 - CONV_W2;
        int m = j >> 9, k = j & 511;
        g_W3t[j] = __float2bfloat16(W3[k * 256 + m]);
    } else {
        int j = i - CONV_W1 - CONV_W2 - CONV_W3;
        g_xh[j] = __float2bfloat16(x[j]);
    }
}

// ---------------- degrees + graph counts ----------------
__global__ void degcnt_k(const int* __restrict__ nidx, const int* __restrict__ eidx,
                         const int* __restrict__ batch) {
    int i = blockIdx.x * blockDim.x + threadIdx.x;
    if (i < N_INC) {
        atomicAdd(&g_degN[nidx[i]], 1);
        atomicAdd(&g_degE[eidx[i]], 1);
    }
    if (i < N_NODES) atomicAdd(&g_cnt[batch[i]], 1.f);
}

// ---------------- segment offsets via block-aggregated atomics ------------------
// Offsets need not be ordered: each block claims a contiguous range with ONE
// atomicAdd, then distributes it with an intra-block exclusive scan.
__global__ void __launch_bounds__(256) off_k() {
    __shared__ int sm[256];
    __shared__ int base;
    const int w = blockIdx.y;
    const int* cnt = w ? g_degN : g_degE;
    int* offs = w ? g_offN : g_offE;
    int* cur  = w ? g_curN : g_curE;
    float* invb = w ? g_dinv : g_binv;
    const int i = blockIdx.x * 256 + threadIdx.x;
    const int t = threadIdx.x;
    const int v = (i < N_EDGES) ? cnt[i] : 0;
    sm[t] = v;
    __syncthreads();
    for (int d = 1; d < 256; d <<= 1) {
        int u = (t >= d) ? sm[t - d] : 0;
        __syncthreads();
        sm[t] += u;
        __syncthreads();
    }
    if (t == 255) base = atomicAdd(&g_tot[w], sm[255]);
    __syncthreads();
    if (i < N_EDGES) {
        int e = base + sm[t] - v;
        offs[i] = e;
        cur[i]  = e;
        invb[i] = v > 0 ? 1.f / (float)v : 0.f;
    }
}

__global__ void build_k(const int* __restrict__ nidx, const int* __restrict__ eidx) {
    int i = blockIdx.x * blockDim.x + threadIdx.x;
    if (i >= N_INC) return;
    const int n = nidx[i], e = eidx[i];
    int pe = atomicAdd(&g_curE[e], 1);
    g_nByE[pe] = n;
    int pn = atomicAdd(&g_curN[n], 1);
    g_eByN[pn] = e;
}

// ---------------- gathers (bf16, 8-deep pipeline) ----------------
__global__ void __launch_bounds__(256) gath_n2e_h(int inSel, int log2q) {
    const uint4* in = (const uint4*)bufh(inSel);
    const int t = threadIdx.x;
    const int j = t & ((1 << log2q) - 1);
    const int e = blockIdx.x * (256 >> log2q) + (t >> log2q);
    const int start = g_offE[e];
    const int d     = g_degE[e];
    float a[8] = {0.f, 0.f, 0.f, 0.f, 0.f, 0.f, 0.f, 0.f};
    int k = 0;
    for (; k + 7 < d; k += 8) {
        int nn[8];
#pragma unroll
        for (int u = 0; u < 8; u++) nn[u] = __ldg(&g_nByE[start + k + u]);
        uint4 vv[8];
#pragma unroll
        for (int u = 0; u < 8; u++) vv[u] = __ldg(&in[((size_t)nn[u] << log2q) + j]);
#pragma unroll
        for (int u = 0; u < 8; u++) acc8(a, vv[u]);
    }
    for (; k + 3 < d; k += 4) {
        int nn[4];
#pragma unroll
        for (int u = 0; u < 4; u++) nn[u] = __ldg(&g_nByE[start + k + u]);
        uint4 vv[4];
#pragma unroll
        for (int u = 0; u < 4; u++) vv[u] = __ldg(&in[((size_t)nn[u] << log2q) + j]);
#pragma unroll
        for (int u = 0; u < 4; u++) acc8(a, vv[u]);
    }
    for (; k < d; k++)
        acc8(a, __ldg(&in[((size_t)__ldg(&g_nByE[start + k]) << log2q) + j]));
    const float bw = g_binv[e];
#pragma unroll
    for (int r = 0; r < 8; r++) a[r] *= bw;
    ((uint4*)g_ef_h)[((size_t)e << log2q) + j] = pack8(a);
}

__global__ void __launch_bounds__(256) gath_e2n_h(
    int outSel, int log2q, int doEpi, const float* __restrict__ bias,
    int doPool, const int* __restrict__ batch) {
    uint4* outb = (uint4*)bufh(outSel);
    const uint4* ef = (const uint4*)g_ef_h;
    const int t = threadIdx.x;
    const int j = t & ((1 << log2q) - 1);
    const int n = blockIdx.x * (256 >> log2q) + (t >> log2q);
    const int start = g_offN[n];
    const int d     = g_degN[n];
    float a[8] = {0.f, 0.f, 0.f, 0.f, 0.f, 0.f, 0.f, 0.f};
    int k = 0;
    for (; k + 7 < d; k += 8) {
        int ee[8];
#pragma unroll
        for (int u = 0; u < 8; u++) ee[u] = __ldg(&g_eByN[start + k + u]);
        uint4 vv[8];
#pragma unroll
        for (int u = 0; u < 8; u++) vv[u] = __ldg(&ef[((size_t)ee[u] << log2q) + j]);
#pragma unroll
        for (int u = 0; u < 8; u++) acc8(a, vv[u]);
    }
    for (; k + 3 < d; k += 4) {
        int ee[4];
#pragma unroll
        for (int u = 0; u < 4; u++) ee[u] = __ldg(&g_eByN[start + k + u]);
        uint4 vv[4];
#pragma unroll
        for (int u = 0; u < 4; u++) vv[u] = __ldg(&ef[((size_t)ee[u] << log2q) + j]);
#pragma unroll
        for (int u = 0; u < 4; u++) acc8(a, vv[u]);
    }
    for (; k < d; k++)
        acc8(a, __ldg(&ef[((size_t)__ldg(&g_eByN[start + k]) << log2q) + j]));
    const float ds = g_dinv[n];
#pragma unroll
    for (int r = 0; r < 8; r++) a[r] *= ds;
    if (doEpi) {
        float4 bb0 = ((const float4*)bias)[2 * j];
        float4 bb1 = ((const float4*)bias)[2 * j + 1];
        a[0] = fmaxf(a[0] + bb0.x, 0.f); a[1] = fmaxf(a[1] + bb0.y, 0.f);
        a[2] = fmaxf(a[2] + bb0.z, 0.f); a[3] = fmaxf(a[3] + bb0.w, 0.f);
        a[4] = fmaxf(a[4] + bb1.x, 0.f); a[5] = fmaxf(a[5] + bb1.y, 0.f);
        a[6] = fmaxf(a[6] + bb1.z, 0.f); a[7] = fmaxf(a[7] + bb1.w, 0.f);
    }
    if (doPool) {
        float* dst = &g_pool[(batch[n] << 8) + 8 * j];
        red4(dst,     make_float4(a[0], a[1], a[2], a[3]));
        red4(dst + 4, make_float4(a[4], a[5], a[6], a[7]));
    } else {
        outb[((size_t)n << log2q) + j] = pack8(a);
    }
}

// ---------------- BF16 GEMM: 3-stage cp.async, 1 sync/iter, ldmatrix ------------
#define HS 20
#define STAGE_U (128 * HS)
#define STAGE_BYTES (STAGE_U * 4)
#define NSTG 3
#define GEMM_SMEM (NSTG * STAGE_BYTES * 2)
__global__ void __launch_bounds__(256) gemm_bf(
    int Asel, int Wsel, const float* __restrict__ bias, int outSel,
    int N, int K, int M, int doEpi) {
    const bf16* A  = bufh(Asel);
    const bf16* Wt = bufh(Wsel);
    bf16* C = bufh(outSel);

    extern __shared__ uint32_t dyn[];
    uint32_t* As_u = dyn;
    uint32_t* Bs_u = dyn + NSTG * STAGE_U;

    const int tid  = threadIdx.x;
    const int lane = tid & 31;
    const int warp = tid >> 5;
    const int wm = (warp & 3) * 32;
    const int wn = (warp >> 2) * 64;
    const int grp = lane >> 2;
    const int tig = lane & 3;

    const int rowBase = blockIdx.x * 128;
    const int colBase = blockIdx.y * 128;

    const int lr  = tid >> 1;
    const int lkb = (tid & 1) * 32;
    const int grow = rowBase + lr;
    const int gcol = colBase + lr;
    const bool aok = grow < N;

    uint32_t smA = (uint32_t)__cvta_generic_to_shared(As_u);
    uint32_t smB = (uint32_t)__cvta_generic_to_shared(Bs_u);
    uint32_t aBase = smA + lr * 80 + lkb;
    uint32_t bBase = smB + lr * 80 + lkb;
    const char* aSrc0 = (const char*)(A + (size_t)(aok ? grow : 0) * K) + lkb;
    const char* bSrc0 = (const char*)(Wt + (size_t)gcol * K) + lkb;

    uint32_t aAddr[2], bAddr[4];
#pragma unroll
    for (int mt = 0; mt < 2; mt++) {
        int row = wm + mt * 16 + ((lane >> 3) & 1) * 8 + (lane & 7);
        aAddr[mt] = smA + (row * HS + (lane >> 4) * 4) * 4;
    }
#pragma unroll
    for (int p = 0; p < 4; p++) {
        int row = wn + p * 16 + ((lane >> 4) & 1) * 8 + (lane & 7);
        bAddr[p] = smB + (row * HS + ((lane >> 3) & 1) * 4) * 4;
    }

    float acc[2][8][4];
#pragma unroll
    for (int mt = 0; mt < 2; mt++)
#pragma unroll
        for (int nt = 0; nt < 8; nt++)
#pragma unroll
            for (int r = 0; r < 4; r++) acc[mt][nt][r] = 0.f;

    const int nst = K >> 5;
#pragma unroll
    for (int s = 0; s < 2; s++) {
        const int off = s * 64;
        cp16(aBase + s * STAGE_BYTES,      aSrc0 + off,      aok);
        cp16(aBase + s * STAGE_BYTES + 16, aSrc0 + off + 16, aok);
        cp16(bBase + s * STAGE_BYTES,      bSrc0 + off,      true);
        cp16(bBase + s * STAGE_BYTES + 16, bSrc0 + off + 16, true);
        CP_COMMIT();
    }

    int st = 0, sl = 2;
    for (int i = 0; i < nst; i++) {
        if (i + 1 < nst) { CP_WAIT1(); } else { CP_WAIT0(); }
        __syncthreads();
        if (i + 2 < nst) {
            const int off = (i + 2) * 64;
            cp16(aBase + sl * STAGE_BYTES,      aSrc0 + off,      aok);
            cp16(aBase + sl * STAGE_BYTES + 16, aSrc0 + off + 16, aok);
            cp16(bBase + sl * STAGE_BYTES,      bSrc0 + off,      true);
            cp16(bBase + sl * STAGE_BYTES + 16, bSrc0 + off + 16, true);
            CP_COMMIT();
        }
        const uint32_t stOff = st * STAGE_BYTES;
#pragma unroll
        for (int kk2 = 0; kk2 < 16; kk2 += 8) {
            const uint32_t kOff = stOff + kk2 * 4;
            uint32_t af[2][4], bq[4][4];
#pragma unroll
            for (int mt = 0; mt < 2; mt++) ldsm4(af[mt], aAddr[mt] + kOff);
#pragma unroll
            for (int p = 0; p < 4; p++)    ldsm4(bq[p],  bAddr[p] + kOff);
#pragma unroll
            for (int mt = 0; mt < 2; mt++)
#pragma unroll
                for (int p = 0; p < 4; p++) {
                    mma_bf16(acc[mt][2 * p],     af[mt], &bq[p][0]);
                    mma_bf16(acc[mt][2 * p + 1], af[mt], &bq[p][2]);
                }
        }
        st = (st == NSTG - 1) ? 0 : st + 1;
        sl = (sl == NSTG - 1) ? 0 : sl + 1;
    }

#pragma unroll
    for (int mt = 0; mt < 2; mt++) {
        const int r0 = rowBase + wm + mt * 16 + grp;
        const int r1 = r0 + 8;
#pragma unroll
        for (int nt = 0; nt < 8; nt++) {
            const int col = colBase + wn + nt * 8 + tig * 2;
            float v0 = acc[mt][nt][0], v1 = acc[mt][nt][1];
            float v2 = acc[mt][nt][2], v3 = acc[mt][nt][3];
            if (doEpi) {
                const float bb0 = bias[col], bb1 = bias[col + 1];
                v0 = fmaxf(v0 + bb0, 0.f); v1 = fmaxf(v1 + bb1, 0.f);
                v2 = fmaxf(v2 + bb0, 0.f); v3 = fmaxf(v3 + bb1, 0.f);
            }
            if (r0 < N)
                *(bf162*)(C + (size_t)r0 * M + col) =
                    __float22bfloat162_rn(make_float2(v0, v1));
            if (r1 < N)
                *(bf162*)(C + (size_t)r1 * M + col) =
                    __float22bfloat162_rn(make_float2(v2, v3));
        }
    }
}

// ---------------- final MLP ----------------
__global__ void __launch_bounds__(256) mlp_k(
    const float* __restrict__ Wl1, const float* __restrict__ bl1,
    const float* __restrict__ Wl2, const float* __restrict__ bl2,
    float* __restrict__ out) {
    __shared__ float sp[256];
    __shared__ float red[128];
    const int g = blockIdx.x;
    const int t = threadIdx.x;

    const float ic = 1.f / fmaxf(g_cnt[g], 1.f);
    sp[t] = g_pool[(g << 8) + t] * ic;
    __syncthreads();

    if (t < 128) {
        float a = bl1[t];
#pragma unroll 8
        for (int k = 0; k < 256; k++) a = fmaf(sp[k], Wl1[k * 128 + t], a);
        red[t] = fmaxf(a, 0.f) * Wl2[t];
    }
    __syncthreads();
    for (int s = 64; s > 0; s >>= 1) {
        if (t < s) red[t] += red[t + s];
        __syncthreads();
    }
    if (t == 0) out[g] = red[0] + bl2[0];
}

extern "C" void kernel_launch(void* const* d_in, const int* in_sizes, int n_in,
                              void* d_out, int out_size) {
    const float* x     = (const float*)d_in[0];
    const int*   hei   = (const int*)d_in[1];    // int32 (JAX x64-disabled)
    const int*   batch = (const int*)d_in[2];
    const float *W1  = (const float*)d_in[3],  *b1  = (const float*)d_in[4];
    const float *W2  = (const float*)d_in[5],  *b2  = (const float*)d_in[6];
    const float *W3  = (const float*)d_in[7],  *b3  = (const float*)d_in[8];
    const float *Wl1 = (const float*)d_in[9],  *bl1 = (const float*)d_in[10];
    const float *Wl2 = (const float*)d_in[11], *bl2 = (const float*)d_in[12];
    const int* nidx = hei;
    const int* eidx = hei + N_INC;
    float* out = (float*)d_out;

    cudaFuncSetAttribute(gemm_bf, cudaFuncAttributeMaxDynamicSharedMemorySize,
                         GEMM_SMEM);

    // ---- setup: init+convert, degrees, 1-kernel offsets, CSR build ----
    init_conv<<<(CONV_TOT + 255) / 256, 256>>>(W1, W2, W3, x);
    degcnt_k<<<(N_INC + 255) / 256, 256>>>(nidx, eidx, batch);
    off_k<<<dim3(OFF_B, 2), 256>>>();
    build_k<<<(N_INC + 255) / 256, 256>>>(nidx, eidx);

    // ---- Layer 1 (gather-first, dim 128 bf16; K=128 -> M=256) ----
    gath_n2e_h<<<N_EDGES / 16, 256>>>(7, 4);
    gath_e2n_h<<<N_NODES / 16, 256>>>(0, 4, 0, nullptr, 0, nullptr);
    gemm_bf<<<dim3(391, 2), 256, GEMM_SMEM>>>(0, 4, b1, 2, N_NODES, 128, 256, 1);

    // ---- Layer 2 (gather-first, dim 256; K=256 -> M=512) ----
    gath_n2e_h<<<N_EDGES / 8, 256>>>(2, 5);
    gath_e2n_h<<<N_NODES / 8, 256>>>(0, 5, 0, nullptr, 0, nullptr);
    gemm_bf<<<dim3(391, 4), 256, GEMM_SMEM>>>(0, 5, b2, 3, N_NODES, 256, 512, 1);

    // ---- Layer 3 (gemm-first; K=512 -> M=256; epi + pool fused into e2n) ----
    gemm_bf<<<dim3(391, 2), 256, GEMM_SMEM>>>(3, 6, nullptr, 0, N_NODES, 512, 256, 0);
    gath_n2e_h<<<N_EDGES / 8, 256>>>(0, 5);
    gath_e2n_h<<<N_NODES / 8, 256>>>(2, 5, 1, b3, 1, batch);

    // ---- MLP head ----
    mlp_k<<<N_GRAPHS, 256>>>(Wl1, bl1, Wl2, bl2, out);
}